// round 10
// baseline (speedup 1.0000x reference)
#include <cuda_runtime.h>
#include <cuda_fp16.h>
#include <cstdint>

// ---------------------------------------------------------------------------
// SO2ConvolutionMoE, FP16 mma.sync:
//   pre_fused (bucket[1 blk, smem histogram] + bias + 3 weight mixes + x->fp16)
//   -> gemm_fused (per-CTA tile derivation; seg1/seg2 use 128x256 tiles with
//      warp 64x64, seg0 uses 128x128 with warp 64x32; 4-stage cp.async,
//      1 CTA/SM).
// ---------------------------------------------------------------------------

#define NEDGES 12288
#define NSYS   16
#define NEXP   8
#define ROWF   2432
#define MAX_GT (112 * 12)     // seg1:4 + seg2:3 + seg0:5 n-blocks per m-tile

__device__ __half g_B0[(size_t)NSYS * 640 * 640];     // [K][N]
__device__ __half g_B1[(size_t)NSYS * 1024 * 1024];
__device__ __half g_B2[(size_t)NSYS * 768 * 768];
__device__ float  g_bias0[NSYS * 640];
__device__ __half g_xh[(size_t)NEDGES * ROWF];
__device__ int    g_list[NSYS * NEDGES];
__device__ int    g_cnt[NSYS];

__device__ __forceinline__ uint32_t h2_as_u32(__half2 h) {
    return *reinterpret_cast<const uint32_t*>(&h);
}

// ---------------------------------------------------------------------------
// Fused preprocessing: one kernel, blocks partitioned by role.
//   block 0: bucket all edges (smem histogram -> g_list, g_cnt)
//   then bias, weight mixes, x->fp16
// ---------------------------------------------------------------------------
#define NB_BKT  1
#define NB_BIAS 3
#define NB_M1   1024     // (1024*1024/4)/256
#define NB_M2   576      // (768*768/4)/256
#define NB_M0   400      // (640*640/4)/256
#define NB_CVT  29184    // (12288*2432/4)/256
#define NB_PRE  (NB_BKT + NB_BIAS + NB_M1 + NB_M2 + NB_M0 + NB_CVT)

template <int MODE>
__device__ __forceinline__ void mix_body(const float* __restrict__ W,
                                         const float* __restrict__ ec, int bi) {
    constexpr int Kin   = (MODE == 0) ? 640 : (MODE == 1) ? 512 : 384;
    constexpr int Nw    = (MODE == 0) ? 640 : (MODE == 1) ? 1024 : 768;
    constexpr int SO2   = (MODE == 0) ? 0 : 1;
    constexpr int KTOT  = SO2 ? 2 * Kin : Kin;
    constexpr int TOTAL = KTOT * Nw;
    constexpr int N4    = Nw / 4;

    __half* Bd = (MODE == 0) ? g_B0 : (MODE == 1) ? g_B1 : g_B2;

    __shared__ float sec[NSYS * NEXP];
    if (threadIdx.x < NSYS * NEXP) sec[threadIdx.x] = ec[threadIdx.x];
    __syncthreads();

    int idx4 = bi * 256 + threadIdx.x;
    if (idx4 >= TOTAL / 4) return;
    int k  = idx4 / N4;
    int jj = idx4 - k * N4;

    float sign = 1.f;
    size_t src4;
    if (!SO2 || k < Kin) {
        src4 = (size_t)k * N4 + jj;
    } else {
        int kk = k - Kin;
        int Nh4 = N4 >> 1;
        if (jj < Nh4) { src4 = (size_t)kk * N4 + Nh4 + jj; sign = -1.f; }
        else          { src4 = (size_t)kk * N4 + (jj - Nh4); }
    }

    const size_t esz4 = (size_t)Kin * N4;
    float4 w[NEXP];
#pragma unroll
    for (int e = 0; e < NEXP; e++) w[e] = ((const float4*)W)[e * esz4 + src4];

#pragma unroll
    for (int s = 0; s < NSYS; s++) {
        float4 a = make_float4(0.f, 0.f, 0.f, 0.f);
#pragma unroll
        for (int e = 0; e < NEXP; e++) {
            float c = sec[s * NEXP + e];
            a.x = fmaf(c, w[e].x, a.x); a.y = fmaf(c, w[e].y, a.y);
            a.z = fmaf(c, w[e].z, a.z); a.w = fmaf(c, w[e].w, a.w);
        }
        uint2 u;
        u.x = h2_as_u32(__floats2half2_rn(sign * a.x, sign * a.y));
        u.y = h2_as_u32(__floats2half2_rn(sign * a.z, sign * a.w));
        *reinterpret_cast<uint2*>(Bd + (size_t)s * TOTAL + (size_t)idx4 * 4) = u;
    }
}

__global__ __launch_bounds__(256) void pre_fused(
    const float* __restrict__ x, const float* __restrict__ ec,
    const int* __restrict__ eb,
    const float* __restrict__ Wm0, const float* __restrict__ bm0,
    const float* __restrict__ Wm1, const float* __restrict__ Wm2) {
    int b = blockIdx.x;

    if (b < NB_BKT) {
        // single-block bucketing: smem histogram gives positions + counts,
        // no global reset kernel needed.
        __shared__ int hcnt[NSYS];
        if (threadIdx.x < NSYS) hcnt[threadIdx.x] = 0;
        __syncthreads();
        for (int i = threadIdx.x; i < NEDGES; i += 256) {
            int s = eb[i];
            int p = atomicAdd(&hcnt[s], 1);
            g_list[s * NEDGES + p] = i;
        }
        __syncthreads();
        if (threadIdx.x < NSYS) g_cnt[threadIdx.x] = hcnt[threadIdx.x];
        return;
    }
    b -= NB_BKT;

    if (b < NB_BIAS) {
        int j = b * 256 + threadIdx.x;
        if (j < 640) {
            float w[NEXP];
#pragma unroll
            for (int e = 0; e < NEXP; e++) w[e] = bm0[e * 640 + j];
#pragma unroll
            for (int s = 0; s < NSYS; s++) {
                float acc = 0.f;
#pragma unroll
                for (int e = 0; e < NEXP; e++)
                    acc = fmaf(ec[s * NEXP + e], w[e], acc);
                g_bias0[s * 640 + j] = acc;
            }
        }
        return;
    }
    b -= NB_BIAS;

    if (b < NB_M1) { mix_body<1>(Wm1, ec, b); return; }
    b -= NB_M1;
    if (b < NB_M2) { mix_body<2>(Wm2, ec, b); return; }
    b -= NB_M2;
    if (b < NB_M0) { mix_body<0>(Wm0, ec, b); return; }
    b -= NB_M0;

    // cvt: x fp32 -> fp16
    {
        int i = b * 256 + threadIdx.x;     // i < NB_CVT*256 == total4 exactly
        float4 v = ((const float4*)x)[i];
        uint2 u;
        u.x = h2_as_u32(__floats2half2_rn(v.x, v.y));
        u.y = h2_as_u32(__floats2half2_rn(v.z, v.w));
        *reinterpret_cast<uint2*>(g_xh + (size_t)i * 4) = u;
    }
}

// ---------------------------------------------------------------------------
// Fused FP16 grouped GEMM.
//   seg1/seg2: 128x256 CTA tile, warp 64x64 (2M x 4N), NFR=8
//   seg0:      128x128 CTA tile, warp 64x32 (2M x 4N), NFR=4
//   KTILE=64, 4-stage cp.async pipeline, 1 barrier / K-iter, 1 CTA/SM.
// ---------------------------------------------------------------------------
#define KTILE 64
#define SA_H 72                  // 64 + 8 pad (halves)
#define STAGES 4
#define A_STAGE (128 * SA_H)     // 9216 halves
#define B_STAGE_MAX (KTILE * 264)
#define SMEM_BYTES ((STAGES * (A_STAGE + B_STAGE_MAX)) * 2 + 512)

__device__ __forceinline__ void mma_f16(float* d, const uint32_t* a, const uint32_t* b) {
    asm volatile(
        "mma.sync.aligned.m16n8k16.row.col.f32.f16.f16.f32 "
        "{%0,%1,%2,%3}, {%4,%5,%6,%7}, {%8,%9}, {%0,%1,%2,%3};\n"
        : "+f"(d[0]), "+f"(d[1]), "+f"(d[2]), "+f"(d[3])
        : "r"(a[0]), "r"(a[1]), "r"(a[2]), "r"(a[3]),
          "r"(b[0]), "r"(b[1]));
}

__device__ __forceinline__ void ldsm_x4(uint32_t* r, uint32_t saddr) {
    asm volatile("ldmatrix.sync.aligned.m8n8.x4.shared.b16 {%0,%1,%2,%3}, [%4];"
        : "=r"(r[0]), "=r"(r[1]), "=r"(r[2]), "=r"(r[3]) : "r"(saddr));
}

__device__ __forceinline__ void ldsm_x4_t(uint32_t* r, uint32_t saddr) {
    asm volatile("ldmatrix.sync.aligned.m8n8.x4.trans.shared.b16 {%0,%1,%2,%3}, [%4];"
        : "=r"(r[0]), "=r"(r[1]), "=r"(r[2]), "=r"(r[3]) : "r"(saddr));
}

__device__ __forceinline__ void cp16(void* dst, const void* src) {
    uint32_t sa = (uint32_t)__cvta_generic_to_shared(dst);
    asm volatile("cp.async.cg.shared.global [%0], [%1], 16;\n" :: "r"(sa), "l"(src));
}

__device__ __forceinline__ void cp16z(void* dst, const void* src, int sz) {
    uint32_t sa = (uint32_t)__cvta_generic_to_shared(dst);
    asm volatile("cp.async.cg.shared.global [%0], [%1], 16, %2;\n" :: "r"(sa), "l"(src), "r"(sz));
}

template <int SEG>
__device__ __forceinline__ void gemm_body(
    float* __restrict__ out, int sys, int m0, int n0, int cnt,
    __half* smh, int tid) {
    constexpr int K    = (SEG == 0) ? 640 : (SEG == 1) ? 1024 : 768;
    constexpr int NT   = (SEG == 0) ? 128 : 256;
    constexpr int XOFF = (SEG == 0) ? 0 : (SEG == 1) ? 640 : 1664;
    constexpr int KT   = K / KTILE;
    constexpr int WN   = NT / 4;          // warp N extent (32 or 64)
    constexpr int NFR  = WN / 8;          // n-frags per warp (4 or 8)
    constexpr int NPAIR = WN / 16;        // ldsm.x4.trans per ks (2 or 4)
    constexpr int SB_H = NT + 8;
    constexpr int B_STAGE = KTILE * SB_H;
    constexpr int SMEM_HALVES = STAGES * (A_STAGE + B_STAGE);

    const __half* Bsys =
        ((SEG == 0) ? g_B0 : (SEG == 1) ? g_B1 : g_B2) + (size_t)sys * K * K;

    __half* sA = smh;                       // [STAGES][128][SA_H]
    __half* sB = smh + STAGES * A_STAGE;    // [STAGES][KTILE][SB_H]
    int*    sE = (int*)(smh + SMEM_HALVES); // [128]

    if (tid < 128) {
        int idx = m0 + tid;
        sE[tid] = (idx < cnt) ? g_list[sys * NEDGES + idx] : -1;
    }
    __syncthreads();

    auto load_tile = [&](int kt, int buf) {
        __half* aBuf = sA + buf * A_STAGE;
        __half* bBuf = sB + buf * B_STAGE;
        // A: 128 rows x 64 halves = 1024 x 16B chunks
#pragma unroll
        for (int i = 0; i < 4; i++) {
            int c = tid + i * 256;
            int row = c >> 3, cc = c & 7;
            int e = sE[row];
            const __half* src = g_xh +
                ((e >= 0) ? ((size_t)e * ROWF + XOFF) : (size_t)0) + kt * KTILE + cc * 8;
            cp16z(aBuf + row * SA_H + cc * 8, src, (e >= 0) ? 16 : 0);
        }
        // B: KTILE rows x NT halves = KTILE*NT/8 x 16B chunks
#pragma unroll
        for (int i = 0; i < KTILE * NT / 8 / 256; i++) {
            int c = tid + i * 256;
            int k = c / (NT / 8), n8 = c % (NT / 8);
            const __half* src = Bsys + (size_t)(kt * KTILE + k) * K + n0 + n8 * 8;
            cp16(bBuf + k * SB_H + n8 * 8, src);
        }
        asm volatile("cp.async.commit_group;\n" ::);
    };

    const int lane = tid & 31, warp = tid >> 5;
    const int wm = warp & 1, wn = warp >> 1;     // 2 M-warps x 4 N-warps
    const int gid = lane >> 2, tig = lane & 3;
    const int l15 = lane & 15, lhi = lane >> 4;

    float acc[4][NFR][4];
#pragma unroll
    for (int a = 0; a < 4; a++)
#pragma unroll
        for (int b = 0; b < NFR; b++)
#pragma unroll
            for (int c = 0; c < 4; c++) acc[a][b][c] = 0.f;

    const uint32_t sA_u = (uint32_t)__cvta_generic_to_shared(sA);
    const uint32_t sB_u = (uint32_t)__cvta_generic_to_shared(sB);

    uint32_t aoff[4], boff[NPAIR];
#pragma unroll
    for (int mt = 0; mt < 4; mt++)
        aoff[mt] = ((wm * 64 + mt * 16 + l15) * SA_H + lhi * 8) * 2;
#pragma unroll
    for (int p = 0; p < NPAIR; p++)
        boff[p] = (l15 * SB_H + wn * WN + p * 16 + lhi * 8) * 2;

    // prologue: 3 stages in flight
    load_tile(0, 0);
    load_tile(1, 1);
    load_tile(2, 2);

    for (int kt = 0; kt < KT; kt++) {
        if (kt + 2 < KT)      asm volatile("cp.async.wait_group 2;\n" ::);
        else if (kt + 1 < KT) asm volatile("cp.async.wait_group 1;\n" ::);
        else                  asm volatile("cp.async.wait_group 0;\n" ::);
        // barrier also guarantees stage (kt-1) reads finished -> safe to
        // overwrite (kt+3)%4 == (kt-1)%4 below.
        __syncthreads();
        if (kt + 3 < KT) load_tile(kt + 3, (kt + 3) % STAGES);

        const int buf = kt % STAGES;
        const uint32_t aB = sA_u + buf * A_STAGE * 2;
        const uint32_t bB = sB_u + buf * B_STAGE * 2;

#pragma unroll
        for (int ks = 0; ks < 4; ks++) {
            uint32_t af[4][4], bf[NFR][2];
#pragma unroll
            for (int mt = 0; mt < 4; mt++)
                ldsm_x4(af[mt], aB + aoff[mt] + ks * 16 * 2);
#pragma unroll
            for (int p = 0; p < NPAIR; p++) {
                uint32_t r[4];
                ldsm_x4_t(r, bB + boff[p] + ks * 16 * SB_H * 2);
                bf[2 * p][0] = r[0]; bf[2 * p][1] = r[1];
                bf[2 * p + 1][0] = r[2]; bf[2 * p + 1][1] = r[3];
            }
#pragma unroll
            for (int mt = 0; mt < 4; mt++)
#pragma unroll
                for (int nt = 0; nt < NFR; nt++)
                    mma_f16(acc[mt][nt], af[mt], bf[nt]);
        }
    }

    // epilogue: scatter rows by edge id, fold bias for seg 0
#pragma unroll
    for (int mt = 0; mt < 4; mt++) {
        int r0 = wm * 64 + mt * 16 + gid;
        int e0 = sE[r0], e1 = sE[r0 + 8];
#pragma unroll
        for (int nt = 0; nt < NFR; nt++) {
            int col = n0 + wn * WN + nt * 8 + tig * 2;
            float b0 = 0.f, b1 = 0.f;
            if (SEG == 0) {
                b0 = g_bias0[sys * 640 + col];
                b1 = g_bias0[sys * 640 + col + 1];
            }
            if (e0 >= 0) {
                float2 v;
                v.x = acc[mt][nt][0] + b0;
                v.y = acc[mt][nt][1] + b1;
                *(float2*)(out + (size_t)e0 * ROWF + XOFF + col) = v;
            }
            if (e1 >= 0) {
                float2 v;
                v.x = acc[mt][nt][2] + b0;
                v.y = acc[mt][nt][3] + b1;
                *(float2*)(out + (size_t)e1 * ROWF + XOFF + col) = v;
            }
        }
    }
}

__global__ __launch_bounds__(256, 1) void gemm_fused(float* __restrict__ out) {
    const int tid = threadIdx.x;

    // --- derive (seg, sys, m0, n0) from blockIdx.x using g_cnt only ---
    __shared__ int scnt[NSYS];
    if (tid < NSYS) scnt[tid] = g_cnt[tid];
    __syncthreads();

    int ms[NSYS];
    int total = 0;
#pragma unroll
    for (int s = 0; s < NSYS; s++) { ms[s] = (scnt[s] + 127) >> 7; total += ms[s]; }

    // order: seg1 (4 nb of 256), seg2 (3 nb of 256), seg0 (5 nb of 128)
    int t = blockIdx.x;
    int seg, nbs_, ntile;
    if (t < 4 * total) { seg = 1; nbs_ = 4; ntile = 256; }
    else {
        t -= 4 * total;
        if (t < 3 * total) { seg = 2; nbs_ = 3; ntile = 256; }
        else {
            t -= 3 * total;
            if (t < 5 * total) { seg = 0; nbs_ = 5; ntile = 128; }
            else return;
        }
    }
    int mt = t / nbs_;
    const int n0 = (t - mt * nbs_) * ntile;
    int sys = 0;
    while (mt >= ms[sys]) { mt -= ms[sys]; sys++; }
    const int m0  = mt << 7;
    const int cnt = scnt[sys];

    extern __shared__ __half smh[];
    if (seg == 1)      gemm_body<1>(out, sys, m0, n0, cnt, smh, tid);
    else if (seg == 2) gemm_body<2>(out, sys, m0, n0, cnt, smh, tid);
    else               gemm_body<0>(out, sys, m0, n0, cnt, smh, tid);
}

// ---------------------------------------------------------------------------
extern "C" void kernel_launch(void* const* d_in, const int* in_sizes, int n_in,
                              void* d_out, int out_size) {
    const float* x   = (const float*)d_in[0];
    const float* ec  = (const float*)d_in[2];
    const int*   eb  = (const int*)d_in[3];
    const float* Wm0 = (const float*)d_in[4];
    const float* bm0 = (const float*)d_in[5];
    const float* Wm1 = (const float*)d_in[6];
    const float* Wm2 = (const float*)d_in[7];
    float* out = (float*)d_out;

    cudaFuncSetAttribute(gemm_fused, cudaFuncAttributeMaxDynamicSharedMemorySize,
                         SMEM_BYTES);

    pre_fused<<<NB_PRE, 256>>>(x, ec, eb, Wm0, bm0, Wm1, Wm2);
    gemm_fused<<<MAX_GT, 256, SMEM_BYTES>>>(out);
}

// round 11
// speedup vs baseline: 1.1475x; 1.1475x over previous
#include <cuda_runtime.h>
#include <cuda_fp16.h>
#include <cstdint>

// ---------------------------------------------------------------------------
// SO2ConvolutionMoE, FP16 mma.sync:
//   pre_fused (bucket[1 blk smem histogram] + bias + 3 weight mixes + x->fp16)
//   -> gemm_fused (all 3 segments, per-CTA tile derivation; 128x128 CTA
//      tiles, warp 64x32, 3-stage cp.async, 2 CTAs/SM, seg-templated body).
// ---------------------------------------------------------------------------

#define NEDGES 12288
#define NSYS   16
#define NEXP   8
#define ROWF   2432
#define MAX_GT (112 * 19)     // seg1:8 + seg2:6 + seg0:5 n-blocks per m-tile

__device__ __half g_B0[(size_t)NSYS * 640 * 640];     // [K][N]
__device__ __half g_B1[(size_t)NSYS * 1024 * 1024];
__device__ __half g_B2[(size_t)NSYS * 768 * 768];
__device__ float  g_bias0[NSYS * 640];
__device__ __half g_xh[(size_t)NEDGES * ROWF];
__device__ int    g_list[NSYS * NEDGES];
__device__ int    g_cnt[NSYS];

__device__ __forceinline__ uint32_t h2_as_u32(__half2 h) {
    return *reinterpret_cast<const uint32_t*>(&h);
}

// ---------------------------------------------------------------------------
// Fused preprocessing: one kernel, blocks partitioned by role.
// ---------------------------------------------------------------------------
#define NB_BKT  1
#define NB_BIAS 3
#define NB_M1   1024     // (1024*1024/4)/256
#define NB_M2   576      // (768*768/4)/256
#define NB_M0   400      // (640*640/4)/256
#define NB_CVT  29184    // (12288*2432/4)/256
#define NB_PRE  (NB_BKT + NB_BIAS + NB_M1 + NB_M2 + NB_M0 + NB_CVT)

template <int MODE>
__device__ __forceinline__ void mix_body(const float* __restrict__ W,
                                         const float* __restrict__ ec, int bi) {
    constexpr int Kin   = (MODE == 0) ? 640 : (MODE == 1) ? 512 : 384;
    constexpr int Nw    = (MODE == 0) ? 640 : (MODE == 1) ? 1024 : 768;
    constexpr int SO2   = (MODE == 0) ? 0 : 1;
    constexpr int KTOT  = SO2 ? 2 * Kin : Kin;
    constexpr int TOTAL = KTOT * Nw;
    constexpr int N4    = Nw / 4;

    __half* Bd = (MODE == 0) ? g_B0 : (MODE == 1) ? g_B1 : g_B2;

    __shared__ float sec[NSYS * NEXP];
    if (threadIdx.x < NSYS * NEXP) sec[threadIdx.x] = ec[threadIdx.x];
    __syncthreads();

    int idx4 = bi * 256 + threadIdx.x;
    if (idx4 >= TOTAL / 4) return;
    int k  = idx4 / N4;
    int jj = idx4 - k * N4;

    float sign = 1.f;
    size_t src4;
    if (!SO2 || k < Kin) {
        src4 = (size_t)k * N4 + jj;
    } else {
        int kk = k - Kin;
        int Nh4 = N4 >> 1;
        if (jj < Nh4) { src4 = (size_t)kk * N4 + Nh4 + jj; sign = -1.f; }
        else          { src4 = (size_t)kk * N4 + (jj - Nh4); }
    }

    const size_t esz4 = (size_t)Kin * N4;
    float4 w[NEXP];
#pragma unroll
    for (int e = 0; e < NEXP; e++) w[e] = ((const float4*)W)[e * esz4 + src4];

#pragma unroll
    for (int s = 0; s < NSYS; s++) {
        float4 a = make_float4(0.f, 0.f, 0.f, 0.f);
#pragma unroll
        for (int e = 0; e < NEXP; e++) {
            float c = sec[s * NEXP + e];
            a.x = fmaf(c, w[e].x, a.x); a.y = fmaf(c, w[e].y, a.y);
            a.z = fmaf(c, w[e].z, a.z); a.w = fmaf(c, w[e].w, a.w);
        }
        uint2 u;
        u.x = h2_as_u32(__floats2half2_rn(sign * a.x, sign * a.y));
        u.y = h2_as_u32(__floats2half2_rn(sign * a.z, sign * a.w));
        *reinterpret_cast<uint2*>(Bd + (size_t)s * TOTAL + (size_t)idx4 * 4) = u;
    }
}

__global__ __launch_bounds__(256) void pre_fused(
    const float* __restrict__ x, const float* __restrict__ ec,
    const int* __restrict__ eb,
    const float* __restrict__ Wm0, const float* __restrict__ bm0,
    const float* __restrict__ Wm1, const float* __restrict__ Wm2) {
    int b = blockIdx.x;

    if (b < NB_BKT) {
        // single-block bucketing: smem histogram -> g_list, g_cnt
        __shared__ int hcnt[NSYS];
        if (threadIdx.x < NSYS) hcnt[threadIdx.x] = 0;
        __syncthreads();
        for (int i = threadIdx.x; i < NEDGES; i += 256) {
            int s = eb[i];
            int p = atomicAdd(&hcnt[s], 1);
            g_list[s * NEDGES + p] = i;
        }
        __syncthreads();
        if (threadIdx.x < NSYS) g_cnt[threadIdx.x] = hcnt[threadIdx.x];
        return;
    }
    b -= NB_BKT;

    if (b < NB_BIAS) {
        int j = b * 256 + threadIdx.x;
        if (j < 640) {
            float w[NEXP];
#pragma unroll
            for (int e = 0; e < NEXP; e++) w[e] = bm0[e * 640 + j];
#pragma unroll
            for (int s = 0; s < NSYS; s++) {
                float acc = 0.f;
#pragma unroll
                for (int e = 0; e < NEXP; e++)
                    acc = fmaf(ec[s * NEXP + e], w[e], acc);
                g_bias0[s * 640 + j] = acc;
            }
        }
        return;
    }
    b -= NB_BIAS;

    if (b < NB_M1) { mix_body<1>(Wm1, ec, b); return; }
    b -= NB_M1;
    if (b < NB_M2) { mix_body<2>(Wm2, ec, b); return; }
    b -= NB_M2;
    if (b < NB_M0) { mix_body<0>(Wm0, ec, b); return; }
    b -= NB_M0;

    // cvt: x fp32 -> fp16
    {
        int i = b * 256 + threadIdx.x;     // i < NB_CVT*256 == total4 exactly
        float4 v = ((const float4*)x)[i];
        uint2 u;
        u.x = h2_as_u32(__floats2half2_rn(v.x, v.y));
        u.y = h2_as_u32(__floats2half2_rn(v.z, v.w));
        *reinterpret_cast<uint2*>(g_xh + (size_t)i * 4) = u;
    }
}

// ---------------------------------------------------------------------------
// Fused FP16 grouped GEMM: 128x128 CTA tile, KTILE=64, 3-stage cp.async,
// 8 warps as 2M x 4N (warp tile 64x32), 2 CTAs/SM, 1 barrier / K-iter.
// ---------------------------------------------------------------------------
#define KTILE 64
#define SA_H 72              // 64 + 8 pad (halves)
#define SB_H 136             // 128 + 8 pad (halves)
#define STAGES 3
#define A_STAGE (128 * SA_H)
#define B_STAGE (KTILE * SB_H)
#define SMEM_HALVES (STAGES * (A_STAGE + B_STAGE))
#define SMEM_BYTES (SMEM_HALVES * 2 + 512)

__device__ __forceinline__ void mma_f16(float* d, const uint32_t* a, const uint32_t* b) {
    asm volatile(
        "mma.sync.aligned.m16n8k16.row.col.f32.f16.f16.f32 "
        "{%0,%1,%2,%3}, {%4,%5,%6,%7}, {%8,%9}, {%0,%1,%2,%3};\n"
        : "+f"(d[0]), "+f"(d[1]), "+f"(d[2]), "+f"(d[3])
        : "r"(a[0]), "r"(a[1]), "r"(a[2]), "r"(a[3]),
          "r"(b[0]), "r"(b[1]));
}

__device__ __forceinline__ void ldsm_x4(uint32_t* r, uint32_t saddr) {
    asm volatile("ldmatrix.sync.aligned.m8n8.x4.shared.b16 {%0,%1,%2,%3}, [%4];"
        : "=r"(r[0]), "=r"(r[1]), "=r"(r[2]), "=r"(r[3]) : "r"(saddr));
}

__device__ __forceinline__ void ldsm_x4_t(uint32_t* r, uint32_t saddr) {
    asm volatile("ldmatrix.sync.aligned.m8n8.x4.trans.shared.b16 {%0,%1,%2,%3}, [%4];"
        : "=r"(r[0]), "=r"(r[1]), "=r"(r[2]), "=r"(r[3]) : "r"(saddr));
}

__device__ __forceinline__ void cp16(void* dst, const void* src) {
    uint32_t sa = (uint32_t)__cvta_generic_to_shared(dst);
    asm volatile("cp.async.cg.shared.global [%0], [%1], 16;\n" :: "r"(sa), "l"(src));
}

__device__ __forceinline__ void cp16z(void* dst, const void* src, int sz) {
    uint32_t sa = (uint32_t)__cvta_generic_to_shared(dst);
    asm volatile("cp.async.cg.shared.global [%0], [%1], 16, %2;\n" :: "r"(sa), "l"(src), "r"(sz));
}

template <int SEG>
__device__ __forceinline__ void gemm_body(
    float* __restrict__ out, int sys, int m0, int n0, int cnt,
    __half* smh, int tid) {
    constexpr int K    = (SEG == 0) ? 640 : (SEG == 1) ? 1024 : 768;
    constexpr int XOFF = (SEG == 0) ? 0 : (SEG == 1) ? 640 : 1664;
    constexpr int KT   = K / KTILE;

    const __half* Bsys =
        ((SEG == 0) ? g_B0 : (SEG == 1) ? g_B1 : g_B2) + (size_t)sys * K * K;

    __half* sA = smh;                       // [STAGES][128][SA_H]
    __half* sB = smh + STAGES * A_STAGE;    // [STAGES][KTILE][SB_H]
    int*    sE = (int*)(smh + SMEM_HALVES); // [128]

    if (tid < 128) {
        int idx = m0 + tid;
        sE[tid] = (idx < cnt) ? g_list[sys * NEDGES + idx] : -1;
    }
    __syncthreads();

    auto load_tile = [&](int kt, int buf) {
        __half* aBuf = sA + buf * A_STAGE;
        __half* bBuf = sB + buf * B_STAGE;
        // A: 128 rows x 64 halves = 1024 x 16B chunks
#pragma unroll
        for (int i = 0; i < 4; i++) {
            int c = tid + i * 256;
            int row = c >> 3, cc = c & 7;
            int e = sE[row];
            const __half* src = g_xh +
                ((e >= 0) ? ((size_t)e * ROWF + XOFF) : (size_t)0) + kt * KTILE + cc * 8;
            cp16z(aBuf + row * SA_H + cc * 8, src, (e >= 0) ? 16 : 0);
        }
        // B: 64 k-rows x 128 halves = 1024 x 16B chunks
#pragma unroll
        for (int i = 0; i < 4; i++) {
            int c = tid + i * 256;
            int k = c >> 4, n8 = c & 15;
            const __half* src = Bsys + (size_t)(kt * KTILE + k) * K + n0 + n8 * 8;
            cp16(bBuf + k * SB_H + n8 * 8, src);
        }
        asm volatile("cp.async.commit_group;\n" ::);
    };

    const int lane = tid & 31, warp = tid >> 5;
    const int wm = warp & 1, wn = warp >> 1;     // 2 M-warps x 4 N-warps
    const int gid = lane >> 2, tig = lane & 3;
    const int l15 = lane & 15, lhi = lane >> 4;

    float acc[4][4][4];
#pragma unroll
    for (int a = 0; a < 4; a++)
#pragma unroll
        for (int b = 0; b < 4; b++)
#pragma unroll
            for (int c = 0; c < 4; c++) acc[a][b][c] = 0.f;

    const uint32_t sA_u = (uint32_t)__cvta_generic_to_shared(sA);
    const uint32_t sB_u = (uint32_t)__cvta_generic_to_shared(sB);

    uint32_t aoff[4], boff[2];
#pragma unroll
    for (int mt = 0; mt < 4; mt++)
        aoff[mt] = ((wm * 64 + mt * 16 + l15) * SA_H + lhi * 8) * 2;
#pragma unroll
    for (int p = 0; p < 2; p++)
        boff[p] = (l15 * SB_H + wn * 32 + p * 16 + lhi * 8) * 2;

    // prologue: 2 stages in flight
    load_tile(0, 0);
    load_tile(1, 1);

    for (int kt = 0; kt < KT; kt++) {
        if (kt + 1 < KT) asm volatile("cp.async.wait_group 1;\n" ::);
        else             asm volatile("cp.async.wait_group 0;\n" ::);
        // barrier also guarantees stage (kt-1) reads finished -> safe to
        // overwrite (kt+2)%3 == (kt-1)%3 below.
        __syncthreads();
        if (kt + 2 < KT) load_tile(kt + 2, (kt + 2) % STAGES);

        const int buf = kt % STAGES;
        const uint32_t aB = sA_u + buf * A_STAGE * 2;
        const uint32_t bB = sB_u + buf * B_STAGE * 2;

#pragma unroll
        for (int ks = 0; ks < 4; ks++) {
            uint32_t af[4][4], bf[4][2];
#pragma unroll
            for (int mt = 0; mt < 4; mt++)
                ldsm_x4(af[mt], aB + aoff[mt] + ks * 16 * 2);
#pragma unroll
            for (int p = 0; p < 2; p++) {
                uint32_t r[4];
                ldsm_x4_t(r, bB + boff[p] + ks * 16 * SB_H * 2);
                bf[2 * p][0] = r[0]; bf[2 * p][1] = r[1];
                bf[2 * p + 1][0] = r[2]; bf[2 * p + 1][1] = r[3];
            }
#pragma unroll
            for (int mt = 0; mt < 4; mt++)
#pragma unroll
                for (int nt = 0; nt < 4; nt++)
                    mma_f16(acc[mt][nt], af[mt], bf[nt]);
        }
    }

    // epilogue: scatter rows by edge id, fold bias for seg 0
#pragma unroll
    for (int mt = 0; mt < 4; mt++) {
        int r0 = wm * 64 + mt * 16 + gid;
        int e0 = sE[r0], e1 = sE[r0 + 8];
#pragma unroll
        for (int nt = 0; nt < 4; nt++) {
            int col = n0 + wn * 32 + nt * 8 + tig * 2;
            float b0 = 0.f, b1 = 0.f;
            if (SEG == 0) {
                b0 = g_bias0[sys * 640 + col];
                b1 = g_bias0[sys * 640 + col + 1];
            }
            if (e0 >= 0) {
                float2 v;
                v.x = acc[mt][nt][0] + b0;
                v.y = acc[mt][nt][1] + b1;
                *(float2*)(out + (size_t)e0 * ROWF + XOFF + col) = v;
            }
            if (e1 >= 0) {
                float2 v;
                v.x = acc[mt][nt][2] + b0;
                v.y = acc[mt][nt][3] + b1;
                *(float2*)(out + (size_t)e1 * ROWF + XOFF + col) = v;
            }
        }
    }
}

__global__ __launch_bounds__(256, 2) void gemm_fused(float* __restrict__ out) {
    const int tid = threadIdx.x;

    // --- derive (seg, sys, m0, n0) from blockIdx.x using g_cnt only ---
    __shared__ int scnt[NSYS];
    if (tid < NSYS) scnt[tid] = g_cnt[tid];
    __syncthreads();

    int ms[NSYS];
    int total = 0;
#pragma unroll
    for (int s = 0; s < NSYS; s++) { ms[s] = (scnt[s] + 127) >> 7; total += ms[s]; }

    // order: seg1 (8 nb), seg2 (6 nb), seg0 (5 nb); m-tiles outer, nb inner
    int t = blockIdx.x;
    int seg, nbs_;
    if (t < 8 * total) { seg = 1; nbs_ = 8; }
    else {
        t -= 8 * total;
        if (t < 6 * total) { seg = 2; nbs_ = 6; }
        else {
            t -= 6 * total;
            if (t < 5 * total) { seg = 0; nbs_ = 5; }
            else return;
        }
    }
    int mt = t / nbs_;
    const int n0 = (t - mt * nbs_) * 128;
    int sys = 0;
    while (mt >= ms[sys]) { mt -= ms[sys]; sys++; }
    const int m0  = mt << 7;
    const int cnt = scnt[sys];

    extern __shared__ __half smh[];
    if (seg == 1)      gemm_body<1>(out, sys, m0, n0, cnt, smh, tid);
    else if (seg == 2) gemm_body<2>(out, sys, m0, n0, cnt, smh, tid);
    else               gemm_body<0>(out, sys, m0, n0, cnt, smh, tid);
}

// ---------------------------------------------------------------------------
extern "C" void kernel_launch(void* const* d_in, const int* in_sizes, int n_in,
                              void* d_out, int out_size) {
    const float* x   = (const float*)d_in[0];
    const float* ec  = (const float*)d_in[2];
    const int*   eb  = (const int*)d_in[3];
    const float* Wm0 = (const float*)d_in[4];
    const float* bm0 = (const float*)d_in[5];
    const float* Wm1 = (const float*)d_in[6];
    const float* Wm2 = (const float*)d_in[7];
    float* out = (float*)d_out;

    cudaFuncSetAttribute(gemm_fused, cudaFuncAttributeMaxDynamicSharedMemorySize,
                         SMEM_BYTES);

    pre_fused<<<NB_PRE, 256>>>(x, ec, eb, Wm0, bm0, Wm1, Wm2);
    gemm_fused<<<MAX_GT, 256, SMEM_BYTES>>>(out);
}

// round 12
// speedup vs baseline: 1.1955x; 1.0419x over previous
#include <cuda_runtime.h>
#include <cuda_fp16.h>
#include <cstdint>

// ---------------------------------------------------------------------------
// SO2ConvolutionMoE, FP16 mma.sync, ONE persistent kernel:
//   phase 1: CTA0 buckets edges (smem histogram); other CTAs do weight mixes
//            (SO(2) recombined, fp16) + bias + x->fp16 (MLP-4 cvt loop)
//   software grid barrier (all CTAs co-resident: launch_bounds(256,2))
//   phase 2: GEMM tiles pulled via atomic ticket; 128x128 CTA tiles,
//            warp 64x32 (2M x 4N), KTILE=64, 3-stage cp.async, 2 CTAs/SM.
// ---------------------------------------------------------------------------

#define NEDGES 12288
#define NSYS   16
#define NEXP   8
#define ROWF   2432

__device__ __half g_B0[(size_t)NSYS * 640 * 640];     // [K][N]
__device__ __half g_B1[(size_t)NSYS * 1024 * 1024];
__device__ __half g_B2[(size_t)NSYS * 768 * 768];
__device__ float  g_bias0[NSYS * 640];
__device__ __half g_xh[(size_t)NEDGES * ROWF];
__device__ int    g_list[NSYS * NEDGES];
__device__ int    g_cnt[NSYS];

// persistent-kernel coordination (replay-safe: release monotonic, arrive self-resets)
__device__ unsigned g_arrive = 0;
__device__ unsigned g_release = 0;
__device__ unsigned g_ticket = 0;

__device__ __forceinline__ uint32_t h2_as_u32(__half2 h) {
    return *reinterpret_cast<const uint32_t*>(&h);
}

__device__ __forceinline__ void grid_barrier(int G) {
    __threadfence();
    __syncthreads();
    if (threadIdx.x == 0) {
        unsigned gen = *((volatile unsigned*)&g_release);
        if (atomicAdd(&g_arrive, 1) == (unsigned)(G - 1)) {
            atomicExch(&g_arrive, 0);
            atomicAdd(&g_release, 1);
        } else {
            while (*((volatile unsigned*)&g_release) == gen) {}
        }
        __threadfence();
    }
    __syncthreads();
}

// ---------------------------------------------------------------------------
// pre-phase role sizes (exclude bucket; bucket = CTA0's job)
// ---------------------------------------------------------------------------
#define NB_BIAS 3
#define NB_M1   1024     // (1024*1024/4)/256
#define NB_M2   576      // (768*768/4)/256
#define NB_M0   400      // (640*640/4)/256
#define NB_REST (NB_BIAS + NB_M1 + NB_M2 + NB_M0)
#define T4_CVT  (NEDGES * ROWF / 4)      // 7,471,104 float4s (multiple of 1024)

template <int MODE>
__device__ __forceinline__ void mix_body(const float* __restrict__ W,
                                         const float* sec, int bi, int tid) {
    constexpr int Kin   = (MODE == 0) ? 640 : (MODE == 1) ? 512 : 384;
    constexpr int Nw    = (MODE == 0) ? 640 : (MODE == 1) ? 1024 : 768;
    constexpr int SO2   = (MODE == 0) ? 0 : 1;
    constexpr int KTOT  = SO2 ? 2 * Kin : Kin;
    constexpr int TOTAL = KTOT * Nw;
    constexpr int N4    = Nw / 4;

    __half* Bd = (MODE == 0) ? g_B0 : (MODE == 1) ? g_B1 : g_B2;

    int idx4 = bi * 256 + tid;
    int k  = idx4 / N4;
    int jj = idx4 - k * N4;

    float sign = 1.f;
    size_t src4;
    if (!SO2 || k < Kin) {
        src4 = (size_t)k * N4 + jj;
    } else {
        int kk = k - Kin;
        int Nh4 = N4 >> 1;
        if (jj < Nh4) { src4 = (size_t)kk * N4 + Nh4 + jj; sign = -1.f; }
        else          { src4 = (size_t)kk * N4 + (jj - Nh4); }
    }

    const size_t esz4 = (size_t)Kin * N4;
    float4 w[NEXP];
#pragma unroll
    for (int e = 0; e < NEXP; e++) w[e] = ((const float4*)W)[e * esz4 + src4];

#pragma unroll
    for (int s = 0; s < NSYS; s++) {
        float4 a = make_float4(0.f, 0.f, 0.f, 0.f);
#pragma unroll
        for (int e = 0; e < NEXP; e++) {
            float c = sec[s * NEXP + e];
            a.x = fmaf(c, w[e].x, a.x); a.y = fmaf(c, w[e].y, a.y);
            a.z = fmaf(c, w[e].z, a.z); a.w = fmaf(c, w[e].w, a.w);
        }
        uint2 u;
        u.x = h2_as_u32(__floats2half2_rn(sign * a.x, sign * a.y));
        u.y = h2_as_u32(__floats2half2_rn(sign * a.z, sign * a.w));
        *reinterpret_cast<uint2*>(Bd + (size_t)s * TOTAL + (size_t)idx4 * 4) = u;
    }
}

// ---------------------------------------------------------------------------
// GEMM building blocks (identical inner loop to the R11 best kernel)
// ---------------------------------------------------------------------------
#define KTILE 64
#define SA_H 72              // 64 + 8 pad (halves)
#define SB_H 136             // 128 + 8 pad (halves)
#define STAGES 3
#define A_STAGE (128 * SA_H)
#define B_STAGE (KTILE * SB_H)
#define SMEM_HALVES (STAGES * (A_STAGE + B_STAGE))
#define SMEM_BYTES (SMEM_HALVES * 2 + 512)

__device__ __forceinline__ void mma_f16(float* d, const uint32_t* a, const uint32_t* b) {
    asm volatile(
        "mma.sync.aligned.m16n8k16.row.col.f32.f16.f16.f32 "
        "{%0,%1,%2,%3}, {%4,%5,%6,%7}, {%8,%9}, {%0,%1,%2,%3};\n"
        : "+f"(d[0]), "+f"(d[1]), "+f"(d[2]), "+f"(d[3])
        : "r"(a[0]), "r"(a[1]), "r"(a[2]), "r"(a[3]),
          "r"(b[0]), "r"(b[1]));
}

__device__ __forceinline__ void ldsm_x4(uint32_t* r, uint32_t saddr) {
    asm volatile("ldmatrix.sync.aligned.m8n8.x4.shared.b16 {%0,%1,%2,%3}, [%4];"
        : "=r"(r[0]), "=r"(r[1]), "=r"(r[2]), "=r"(r[3]) : "r"(saddr));
}

__device__ __forceinline__ void ldsm_x4_t(uint32_t* r, uint32_t saddr) {
    asm volatile("ldmatrix.sync.aligned.m8n8.x4.trans.shared.b16 {%0,%1,%2,%3}, [%4];"
        : "=r"(r[0]), "=r"(r[1]), "=r"(r[2]), "=r"(r[3]) : "r"(saddr));
}

__device__ __forceinline__ void cp16(void* dst, const void* src) {
    uint32_t sa = (uint32_t)__cvta_generic_to_shared(dst);
    asm volatile("cp.async.cg.shared.global [%0], [%1], 16;\n" :: "r"(sa), "l"(src));
}

__device__ __forceinline__ void cp16z(void* dst, const void* src, int sz) {
    uint32_t sa = (uint32_t)__cvta_generic_to_shared(dst);
    asm volatile("cp.async.cg.shared.global [%0], [%1], 16, %2;\n" :: "r"(sa), "l"(src), "r"(sz));
}

template <int SEG>
__device__ __forceinline__ void gemm_body(
    float* __restrict__ out, int sys, int m0, int n0, int cnt,
    __half* smh, int tid) {
    constexpr int K    = (SEG == 0) ? 640 : (SEG == 1) ? 1024 : 768;
    constexpr int XOFF = (SEG == 0) ? 0 : (SEG == 1) ? 640 : 1664;
    constexpr int KT   = K / KTILE;

    const __half* Bsys =
        ((SEG == 0) ? g_B0 : (SEG == 1) ? g_B1 : g_B2) + (size_t)sys * K * K;

    __half* sA = smh;                       // [STAGES][128][SA_H]
    __half* sB = smh + STAGES * A_STAGE;    // [STAGES][KTILE][SB_H]
    int*    sE = (int*)(smh + SMEM_HALVES); // [128]

    if (tid < 128) {
        int idx = m0 + tid;
        sE[tid] = (idx < cnt) ? g_list[sys * NEDGES + idx] : -1;
    }
    __syncthreads();

    auto load_tile = [&](int kt, int buf) {
        __half* aBuf = sA + buf * A_STAGE;
        __half* bBuf = sB + buf * B_STAGE;
#pragma unroll
        for (int i = 0; i < 4; i++) {
            int c = tid + i * 256;
            int row = c >> 3, cc = c & 7;
            int e = sE[row];
            const __half* src = g_xh +
                ((e >= 0) ? ((size_t)e * ROWF + XOFF) : (size_t)0) + kt * KTILE + cc * 8;
            cp16z(aBuf + row * SA_H + cc * 8, src, (e >= 0) ? 16 : 0);
        }
#pragma unroll
        for (int i = 0; i < 4; i++) {
            int c = tid + i * 256;
            int k = c >> 4, n8 = c & 15;
            const __half* src = Bsys + (size_t)(kt * KTILE + k) * K + n0 + n8 * 8;
            cp16(bBuf + k * SB_H + n8 * 8, src);
        }
        asm volatile("cp.async.commit_group;\n" ::);
    };

    const int lane = tid & 31, warp = tid >> 5;
    const int wm = warp & 1, wn = warp >> 1;     // 2 M-warps x 4 N-warps
    const int gid = lane >> 2, tig = lane & 3;
    const int l15 = lane & 15, lhi = lane >> 4;

    float acc[4][4][4];
#pragma unroll
    for (int a = 0; a < 4; a++)
#pragma unroll
        for (int b = 0; b < 4; b++)
#pragma unroll
            for (int c = 0; c < 4; c++) acc[a][b][c] = 0.f;

    const uint32_t sA_u = (uint32_t)__cvta_generic_to_shared(sA);
    const uint32_t sB_u = (uint32_t)__cvta_generic_to_shared(sB);

    uint32_t aoff[4], boff[2];
#pragma unroll
    for (int mt = 0; mt < 4; mt++)
        aoff[mt] = ((wm * 64 + mt * 16 + l15) * SA_H + lhi * 8) * 2;
#pragma unroll
    for (int p = 0; p < 2; p++)
        boff[p] = (l15 * SB_H + wn * 32 + p * 16 + lhi * 8) * 2;

    load_tile(0, 0);
    load_tile(1, 1);

    for (int kt = 0; kt < KT; kt++) {
        if (kt + 1 < KT) asm volatile("cp.async.wait_group 1;\n" ::);
        else             asm volatile("cp.async.wait_group 0;\n" ::);
        __syncthreads();
        if (kt + 2 < KT) load_tile(kt + 2, (kt + 2) % STAGES);

        const int buf = kt % STAGES;
        const uint32_t aB = sA_u + buf * A_STAGE * 2;
        const uint32_t bB = sB_u + buf * B_STAGE * 2;

#pragma unroll
        for (int ks = 0; ks < 4; ks++) {
            uint32_t af[4][4], bf[4][2];
#pragma unroll
            for (int mt = 0; mt < 4; mt++)
                ldsm_x4(af[mt], aB + aoff[mt] + ks * 16 * 2);
#pragma unroll
            for (int p = 0; p < 2; p++) {
                uint32_t r[4];
                ldsm_x4_t(r, bB + boff[p] + ks * 16 * SB_H * 2);
                bf[2 * p][0] = r[0]; bf[2 * p][1] = r[1];
                bf[2 * p + 1][0] = r[2]; bf[2 * p + 1][1] = r[3];
            }
#pragma unroll
            for (int mt = 0; mt < 4; mt++)
#pragma unroll
                for (int nt = 0; nt < 4; nt++)
                    mma_f16(acc[mt][nt], af[mt], bf[nt]);
        }
    }

#pragma unroll
    for (int mt = 0; mt < 4; mt++) {
        int r0 = wm * 64 + mt * 16 + gid;
        int e0 = sE[r0], e1 = sE[r0 + 8];
#pragma unroll
        for (int nt = 0; nt < 4; nt++) {
            int col = n0 + wn * 32 + nt * 8 + tig * 2;
            float b0 = 0.f, b1 = 0.f;
            if (SEG == 0) {
                b0 = g_bias0[sys * 640 + col];
                b1 = g_bias0[sys * 640 + col + 1];
            }
            if (e0 >= 0) {
                float2 v;
                v.x = acc[mt][nt][0] + b0;
                v.y = acc[mt][nt][1] + b1;
                *(float2*)(out + (size_t)e0 * ROWF + XOFF + col) = v;
            }
            if (e1 >= 0) {
                float2 v;
                v.x = acc[mt][nt][2] + b0;
                v.y = acc[mt][nt][3] + b1;
                *(float2*)(out + (size_t)e1 * ROWF + XOFF + col) = v;
            }
        }
    }
}

// ---------------------------------------------------------------------------
// The persistent fused kernel
// ---------------------------------------------------------------------------
__global__ __launch_bounds__(256, 2) void fused_all(
    const float* __restrict__ x, const float* __restrict__ ec,
    const int* __restrict__ eb,
    const float* __restrict__ Wm0, const float* __restrict__ bm0,
    const float* __restrict__ Wm1, const float* __restrict__ Wm2,
    float* __restrict__ out, int G) {
    const int tid = threadIdx.x;
    const int bid = blockIdx.x;

    __shared__ float sec[NSYS * NEXP];
    __shared__ int   hcnt[NSYS];
    __shared__ int   scnt[NSYS];
    __shared__ int   s_t;

    if (tid < NSYS * NEXP) sec[tid] = ec[tid];
    if (bid == 0 && tid == 0) g_ticket = 0;
    if (bid == 0 && tid < NSYS) hcnt[tid] = 0;
    __syncthreads();

    // ---------------- phase 1: preprocessing ----------------
    if (bid == 0) {
        // bucket edges -> per-system lists + counts (smem histogram)
        for (int i = tid; i < NEDGES; i += 256) {
            int s = eb[i];
            int p = atomicAdd(&hcnt[s], 1);
            g_list[s * NEDGES + p] = i;
        }
        __syncthreads();
        if (tid < NSYS) g_cnt[tid] = hcnt[tid];
    } else {
        // weight mixes + bias, grid-strided over role units
        for (int b = bid - 1; b < NB_REST; b += G - 1) {
            if (b < NB_BIAS) {
                int j = b * 256 + tid;
                if (j < 640) {
                    float w[NEXP];
#pragma unroll
                    for (int e = 0; e < NEXP; e++) w[e] = bm0[e * 640 + j];
#pragma unroll
                    for (int s = 0; s < NSYS; s++) {
                        float acc = 0.f;
#pragma unroll
                        for (int e = 0; e < NEXP; e++)
                            acc = fmaf(sec[s * NEXP + e], w[e], acc);
                        g_bias0[s * 640 + j] = acc;
                    }
                }
            } else if (b < NB_BIAS + NB_M1) {
                mix_body<1>(Wm1, sec, b - NB_BIAS, tid);
            } else if (b < NB_BIAS + NB_M1 + NB_M2) {
                mix_body<2>(Wm2, sec, b - NB_BIAS - NB_M1, tid);
            } else {
                mix_body<0>(Wm0, sec, b - NB_BIAS - NB_M1 - NB_M2, tid);
            }
        }
        // cvt x fp32->fp16, 4 independent float4s in flight per thread (MLP 4)
        for (int base = (bid - 1) * 1024; base < T4_CVT; base += (G - 1) * 1024) {
            float4 v[4];
#pragma unroll
            for (int u = 0; u < 4; u++)
                v[u] = ((const float4*)x)[base + u * 256 + tid];
#pragma unroll
            for (int u = 0; u < 4; u++) {
                uint2 o;
                o.x = h2_as_u32(__floats2half2_rn(v[u].x, v[u].y));
                o.y = h2_as_u32(__floats2half2_rn(v[u].z, v[u].w));
                *reinterpret_cast<uint2*>(g_xh + (size_t)(base + u * 256 + tid) * 4) = o;
            }
        }
    }

    // ---------------- grid barrier ----------------
    grid_barrier(G);

    // ---------------- phase 2: GEMM via ticket ----------------
    if (tid < NSYS) scnt[tid] = g_cnt[tid];
    __syncthreads();
    int total = 0;
#pragma unroll
    for (int s = 0; s < NSYS; s++) total += (scnt[s] + 127) >> 7;
    const int ngt = 19 * total;

    extern __shared__ __half smh[];

    while (true) {
        __syncthreads();                     // protect s_t + smem reuse
        if (tid == 0) s_t = (int)atomicAdd(&g_ticket, 1);
        __syncthreads();
        int t = s_t;
        if (t >= ngt) break;

        int seg, nbs_;
        if (t < 8 * total) { seg = 1; nbs_ = 8; }
        else {
            t -= 8 * total;
            if (t < 6 * total) { seg = 2; nbs_ = 6; }
            else { t -= 6 * total; seg = 0; nbs_ = 5; }
        }
        int mt = t / nbs_;
        const int n0 = (t - mt * nbs_) * 128;
        int sys = 0, msv;
        while (mt >= (msv = ((scnt[sys] + 127) >> 7))) { mt -= msv; sys++; }
        const int m0  = mt << 7;
        const int cnt = scnt[sys];

        if (seg == 1)      gemm_body<1>(out, sys, m0, n0, cnt, smh, tid);
        else if (seg == 2) gemm_body<2>(out, sys, m0, n0, cnt, smh, tid);
        else               gemm_body<0>(out, sys, m0, n0, cnt, smh, tid);
    }
}

// ---------------------------------------------------------------------------
extern "C" void kernel_launch(void* const* d_in, const int* in_sizes, int n_in,
                              void* d_out, int out_size) {
    const float* x   = (const float*)d_in[0];
    const float* ec  = (const float*)d_in[2];
    const int*   eb  = (const int*)d_in[3];
    const float* Wm0 = (const float*)d_in[4];
    const float* bm0 = (const float*)d_in[5];
    const float* Wm1 = (const float*)d_in[6];
    const float* Wm2 = (const float*)d_in[7];
    float* out = (float*)d_out;

    static int G = [] {
        int nsm = 0;
        cudaDeviceGetAttribute(&nsm, cudaDevAttrMultiProcessorCount, 0);
        cudaFuncSetAttribute(fused_all,
                             cudaFuncAttributeMaxDynamicSharedMemorySize, SMEM_BYTES);
        return nsm * 2;
    }();

    fused_all<<<G, 256, SMEM_BYTES>>>(x, ec, eb, Wm0, bm0, Wm1, Wm2, out, G);
}